// round 14
// baseline (speedup 1.0000x reference)
#include <cuda_runtime.h>
#include <cuda_bf16.h>

// MultiHashtable4d: 16-level 4D hash-grid encode.
//   out[n, l*2 + c] = sum_{16 corners} w_corner * data[l, index(corner), c]
//
// R14: L1tex-wavefront-bound (33.5M random 8B gathers = 33.5M wavefronts).
// Squeeze issue gaps: 32-bit folded modulo (T = 2^19 + delta), factored
// corner indices (hzw/dzw/weight pair products hoisted), and a double-
// buffered quad pipeline so 8 gathers stay in flight while accumulating.
//
// Layout: warp = (level, 32 points), block = 4 levels x 32 points; level
// constants and hash/direct branch warp-uniform; smem-staged coalesced out.
//
// Bit-exactness vs the JAX reference:
//  * "+1" corner = trunc(fp32(f + 1.0f)) (fp32 add may round up across an
//    integer boundary) -- replicated exactly.
//  * divisions via __fdiv_rn. Hash/mod arithmetic exact integer congruence.
// entrys_num dtype sniffed at runtime (int64 storage has zero hi-words).

#define LVL 16

__global__ void __launch_bounds__(128, 12) mh4d_kernel(
    const float* __restrict__ xyz,         // [N,3]
    const float* __restrict__ tt,          // [N,1]
    const float2* __restrict__ data,       // [L,T] of float2 (f=2)
    const float* __restrict__ bounds,      // [2,4]
    const float* __restrict__ es,          // [L,4] entrys_size (f32)
    const int*   __restrict__ en_raw,      // [L,4] entrys_num (i32 or i64 storage)
    float2* __restrict__ out,              // [N,L] of float2
    int N, unsigned Tsz, unsigned long long magic,
    int fold_ok_host, unsigned m32, unsigned delta, unsigned deltaT)
{
    __shared__ float  s_es[LVL * 4];
    __shared__ int    s_en[LVL * 4];
    __shared__ int    s_hash[LVL];
    __shared__ float  s_b0[4];
    __shared__ int    s_is64;
    __shared__ int    s_fold;
    __shared__ float2 s_out[4][33];        // [warp(level)][point], padded

    const int tid  = threadIdx.x;
    const int wid  = tid >> 5;
    const int lane = tid & 31;

    if (tid == 0) {
        // entrys_num[0] = [16,16,16,100]; int64 storage viewed as i32 has
        // zero odd words. Reads in-bounds for either layout.
        s_is64 = (en_raw[1] == 0 && en_raw[3] == 0 &&
                  en_raw[5] == 0 && en_raw[7] == 0) ? 1 : 0;
    }
    if (tid < LVL * 4) s_es[tid] = es[tid];
    if (tid < 4)       s_b0[tid] = bounds[tid];
    __syncthreads();
    if (tid < LVL * 4) s_en[tid] = s_is64 ? en_raw[2 * tid] : en_raw[tid];
    __syncthreads();
    if (tid == 0) {
        // first level with prod(entrys_num) > T starts hashing (prefix-OR
        // reproduces the reference's break).
        int acc = 0, mx = 0;
        #pragma unroll
        for (int i = 0; i < LVL; i++) {
            long long p = (long long)s_en[4*i+0] * s_en[4*i+1]
                        * s_en[4*i+2] * s_en[4*i+3];
            acc |= (p > (long long)Tsz) ? 1 : 0;
            s_hash[i] = acc;
            mx = max(mx, max(max(s_en[4*i+0], s_en[4*i+1]),
                             max(s_en[4*i+2], s_en[4*i+3])));
        }
        // folded mod needs h < 2^38: max dim * 83492791 < 2^38 -> dim <= 3294
        s_fold = (fold_ok_host && mx <= 3294) ? 1 : 0;
    }
    __syncthreads();

    // block -> (point group, level group); warp -> one level, lane -> point
    const int pg = blockIdx.x >> 2;
    const int lg = blockIdx.x & 3;
    const int l  = lg * 4 + wid;           // warp-uniform
    int n = pg * 32 + lane;
    const bool valid = (n < N);
    if (n >= N) n = N - 1;                 // stay in-bounds, no early exit

    const float px = xyz[3 * n + 0];
    const float py = xyz[3 * n + 1];
    const float pz = xyz[3 * n + 2];
    // t -= start_frame/(total_frame-1); bounds[0][3]=start_frame/total_frame,
    // en[0][3]=total_frame -> shift = b0w*nt/(nt-1). (= 0 here.)
    const float nt = (float)s_en[3];
    const float pw = tt[n] - __fdiv_rn(s_b0[3] * nt, nt - 1.0f);

    // warp-uniform level constants
    const float es0 = s_es[4*l+0], es1 = s_es[4*l+1];
    const float es2 = s_es[4*l+2], es3 = s_es[4*l+3];
    const int   en0 = s_en[4*l+0], en1 = s_en[4*l+1];
    const int   en2 = s_en[4*l+2], en3 = s_en[4*l+3];
    const bool  ish = (s_hash[l] != 0);
    const bool  fold = (s_fold != 0);

    const float fx = __fdiv_rn(px - s_b0[0], es0);
    const float fy = __fdiv_rn(py - s_b0[1], es1);
    const float fz = __fdiv_rn(pz - s_b0[2], es2);
    const float fw = __fdiv_rn(pw - s_b0[3], es3);

    // low corner: trunc(f) (coords >= 0); high corner: trunc(fp32(f+1.0f))
    // (NOT low+1: the fp32 add may round up across an integer boundary).
    const int bx = (int)fx, by = (int)fy, bz = (int)fz, bw = (int)fw;
    const int hxc = (int)__fadd_rn(fx, 1.0f);
    const int hyc = (int)__fadd_rn(fy, 1.0f);
    const int hzc = (int)__fadd_rn(fz, 1.0f);
    const int hwc = (int)__fadd_rn(fw, 1.0f);

    const float ox = fx - (float)bx;
    const float oy = fy - (float)by;
    const float oz = fz - (float)bz;
    const float ow = fw - (float)bw;

    int cxs[2], cys[2], czs[2], cws[2];
    cxs[0] = min(max(bx, 0), en0 - 1);  cxs[1] = min(max(hxc, 0), en0 - 1);
    cys[0] = min(max(by, 0), en1 - 1);  cys[1] = min(max(hyc, 0), en1 - 1);
    czs[0] = min(max(bz, 0), en2 - 1);  czs[1] = min(max(hzc, 0), en2 - 1);
    cws[0] = min(max(bw, 0), en3 - 1);  cws[1] = min(max(hwc, 0), en3 - 1);

    float wxs[2], wys[2], wzs[2], wws[2];
    wxs[0] = __saturatef(1.0f - ox); wxs[1] = __saturatef(ox);
    wys[0] = __saturatef(1.0f - oy); wys[1] = __saturatef(oy);
    wzs[0] = __saturatef(1.0f - oz); wzs[1] = __saturatef(oz);
    wws[0] = __saturatef(1.0f - ow); wws[1] = __saturatef(ow);

    // factored hash partials (6 u64 mults total) and zw XOR combos
    const unsigned long long hyv0 = (unsigned long long)(unsigned)cys[0] * 19349663ull;
    const unsigned long long hyv1 = (unsigned long long)(unsigned)cys[1] * 19349663ull;
    const unsigned long long hzv0 = (unsigned long long)(unsigned)czs[0] * 83492791ull;
    const unsigned long long hzv1 = (unsigned long long)(unsigned)czs[1] * 83492791ull;
    const unsigned long long hwv0 = (unsigned long long)(unsigned)cws[0] * 73856093ull;
    const unsigned long long hwv1 = (unsigned long long)(unsigned)cws[1] * 73856093ull;
    unsigned long long hzw[4];
    hzw[0] = hzv0 ^ hwv0;  hzw[1] = hzv0 ^ hwv1;
    hzw[2] = hzv1 ^ hwv0;  hzw[3] = hzv1 ^ hwv1;

    // factored direct partials (direct levels: prod <= T, fits u32)
    const unsigned e23 = (unsigned)en2 * (unsigned)en3;
    unsigned dzw[4];
    dzw[0] = (unsigned)czs[0] * (unsigned)en3 + (unsigned)cws[0];
    dzw[1] = (unsigned)czs[0] * (unsigned)en3 + (unsigned)cws[1];
    dzw[2] = (unsigned)czs[1] * (unsigned)en3 + (unsigned)cws[0];
    dzw[3] = (unsigned)czs[1] * (unsigned)en3 + (unsigned)cws[1];

    // pair weights
    float wxy[4], wzw[4];
    wxy[0] = wxs[0] * wys[0];  wxy[1] = wxs[0] * wys[1];
    wxy[2] = wxs[1] * wys[0];  wxy[3] = wxs[1] * wys[1];
    wzw[0] = wzs[0] * wws[0];  wzw[1] = wzs[0] * wws[1];
    wzw[2] = wzs[1] * wws[0];  wzw[3] = wzs[1] * wws[1];

    const float2* tab = data + (size_t)Tsz * (unsigned)l;

    // per-quad bases: quad p = (x-bit = p>>1, y-bit = p&1)
    unsigned long long hb[4];
    unsigned db[4];
    #pragma unroll
    for (int p = 0; p < 4; p++) {
        const int xb = p >> 1, yb = p & 1;
        hb[p] = (unsigned long long)(unsigned)cxs[xb] ^ (yb ? hyv1 : hyv0);
        db[p] = ((unsigned)cxs[xb] * (unsigned)en1 + (unsigned)cys[yb]) * e23;
    }

    // corner index (warp-uniform path selection)
    auto corner_idx = [&](int p, int j) -> unsigned {
        if (ish) {
            const unsigned long long h = hb[p] ^ hzw[j];
            if (fold) {
                // h < 2^38, T = 2^19 + delta: h = a*2^19 + b ==>
                // h mod T == (b + delta*(T - a)) mod T, operand < 2^24.
                const unsigned lo = (unsigned)h;
                const unsigned hi = (unsigned)(h >> 32);
                const unsigned a  = (hi << 13) | (lo >> 19);
                const unsigned b  = lo & 0x7FFFFu;
                unsigned v = b + deltaT - delta * a;   // = b + delta*(T-a)
                unsigned q = __umulhi(v, m32);         // m32 = floor(2^32/T)
                unsigned r = v - q * Tsz;              // r in [0, 2T)
                if (r >= Tsz) r -= Tsz;
                return r;
            } else {
                unsigned long long q = __umul64hi(h, magic);
                unsigned long long r = h - q * (unsigned long long)Tsz;
                if (r >= (unsigned long long)Tsz) r -= (unsigned long long)Tsz;
                if (r >= (unsigned long long)Tsz) r -= (unsigned long long)Tsz;
                return (unsigned)r;
            }
        } else {
            return db[p] + dzw[j];
        }
    };

    float acc0 = 0.0f, acc1 = 0.0f;
    float2 buf[2][4];                       // double-buffered quads

    #pragma unroll
    for (int j = 0; j < 4; j++) buf[0][j] = __ldcg(&tab[corner_idx(0, j)]);

    #pragma unroll
    for (int p = 0; p < 4; p++) {
        const int cur = p & 1, nxt = cur ^ 1;
        if (p < 3) {                        // issue next quad before consuming
            #pragma unroll
            for (int j = 0; j < 4; j++)
                buf[nxt][j] = __ldcg(&tab[corner_idx(p + 1, j)]);
        }
        const float wp = wxy[p];
        #pragma unroll
        for (int j = 0; j < 4; j++) {
            const float w = wp * wzw[j];
            acc0 += w * buf[cur][j].x;
            acc1 += w * buf[cur][j].y;
        }
    }

    // stage result; remap to fully-coalesced, sector-dense stores
    s_out[wid][lane] = make_float2(acc0, acc1);
    __syncthreads();

    const int qp = tid >> 2;                // point within group (0..31)
    const int rp = tid & 3;                 // level within block (0..3)
    const int nq = pg * 32 + qp;
    if (nq < N && valid) {
        out[(size_t)nq * 16 + lg * 4 + rp] = s_out[rp][qp];
    }
}

extern "C" void kernel_launch(void* const* d_in, const int* in_sizes, int n_in,
                              void* d_out, int out_size) {
    const float*  xyz    = (const float*)d_in[0];
    const float*  tt     = (const float*)d_in[1];
    const float2* data   = (const float2*)d_in[2];
    const float*  bounds = (const float*)d_in[3];
    // d_in[4] (offsets) is the fixed 16x4 binary corner table -> hard-coded
    const float*  es     = (const float*)d_in[5];
    const int*    en     = (const int*)d_in[6];
    // d_in[7..9]: start_hash / start_frame / total_frame -> derived on device

    const int N = in_sizes[0] / 3;                        // xyz is [N,3]
    const int LF = out_size / N;                          // = L*f = 32
    const unsigned Tsz = (unsigned)(in_sizes[2] / LF);    // data is [L,T,f]
    const unsigned long long magic = 0xFFFFFFFFFFFFFFFFull / (unsigned long long)Tsz;

    // folded-mod constants: valid when 2^19 <= T < 2^19 + 2048
    const int fold_ok = (Tsz >= (1u << 19)) && (Tsz - (1u << 19) < 2048u);
    const unsigned delta  = fold_ok ? (Tsz - (1u << 19)) : 0u;
    const unsigned deltaT = delta * Tsz;
    const unsigned m32    = (unsigned)(0x100000000ull / (unsigned long long)Tsz);

    const int pgroups = (N + 31) / 32;
    const int blocks = pgroups * 4;        // 4 level-groups of 4 levels each
    mh4d_kernel<<<blocks, 128>>>(xyz, tt, data, bounds, es, en,
                                 (float2*)d_out, N, Tsz, magic,
                                 fold_ok, m32, delta, deltaT);
}

// round 15
// speedup vs baseline: 1.0193x; 1.0193x over previous
#include <cuda_runtime.h>
#include <cuda_bf16.h>

// MultiHashtable4d: 16-level 4D hash-grid encode.
//   out[n, l*2 + c] = sum_{16 corners} w_corner * data[l, index(corner), c]
//
// R15: R13's exact load structure (2 batches of 8 gathers, x-major corner
// order -- R14's 4x4 pipeline regressed) + 32-bit index math:
//   * hash partials kept as (lo32, hi<64) pairs (all partials < 2^38),
//   * folded modulo: T = 2^19 + delta, h = a*2^19 + b  ==>
//     h mod T == (b + delta*(T-a)) mod T, finished by one 32-bit Barrett.
// Exact u64 Barrett fallback if the fold preconditions fail (checked at
// runtime: T in [2^19, 2^19+2048), all grid dims <= 3293 so h < 2^38).
//
// Layout: warp = (level, 32 points), block = 4 levels x 32 points; level
// constants and hash/direct branch warp-uniform; smem-staged coalesced out.
//
// Bit-exactness vs the JAX reference:
//  * "+1" corner = trunc(fp32(f + 1.0f)) (fp32 add may round up across an
//    integer boundary) -- replicated exactly.
//  * divisions via __fdiv_rn; all modulo paths exact integer congruence.
// entrys_num dtype sniffed at runtime (int64 storage has zero hi-words).

#define LVL 16

__global__ void __launch_bounds__(128, 12) mh4d_kernel(
    const float* __restrict__ xyz,         // [N,3]
    const float* __restrict__ tt,          // [N,1]
    const float2* __restrict__ data,       // [L,T] of float2 (f=2)
    const float* __restrict__ bounds,      // [2,4]
    const float* __restrict__ es,          // [L,4] entrys_size (f32)
    const int*   __restrict__ en_raw,      // [L,4] entrys_num (i32 or i64 storage)
    float2* __restrict__ out,              // [N,L] of float2
    int N, unsigned Tsz, unsigned long long magic,
    int fold_ok_host, unsigned m32, unsigned delta, unsigned deltaT)
{
    __shared__ float  s_es[LVL * 4];
    __shared__ int    s_en[LVL * 4];
    __shared__ int    s_hash[LVL];
    __shared__ float  s_b0[4];
    __shared__ int    s_is64;
    __shared__ int    s_fold;
    __shared__ float2 s_out[4][33];        // [warp(level)][point], padded

    const int tid  = threadIdx.x;
    const int wid  = tid >> 5;
    const int lane = tid & 31;

    if (tid == 0) {
        // entrys_num[0] = [16,16,16,100]; int64 storage viewed as i32 has
        // zero odd words. Reads in-bounds for either layout.
        s_is64 = (en_raw[1] == 0 && en_raw[3] == 0 &&
                  en_raw[5] == 0 && en_raw[7] == 0) ? 1 : 0;
    }
    if (tid < LVL * 4) s_es[tid] = es[tid];
    if (tid < 4)       s_b0[tid] = bounds[tid];
    __syncthreads();
    if (tid < LVL * 4) s_en[tid] = s_is64 ? en_raw[2 * tid] : en_raw[tid];
    __syncthreads();
    if (tid == 0) {
        // first level with prod(entrys_num) > T starts hashing (prefix-OR
        // reproduces the reference's break).
        int acc = 0, mx = 0;
        #pragma unroll
        for (int i = 0; i < LVL; i++) {
            long long p = (long long)s_en[4*i+0] * s_en[4*i+1]
                        * s_en[4*i+2] * s_en[4*i+3];
            acc |= (p > (long long)Tsz) ? 1 : 0;
            s_hash[i] = acc;
            mx = max(mx, max(max(s_en[4*i+0], s_en[4*i+1]),
                             max(s_en[4*i+2], s_en[4*i+3])));
        }
        // fold needs h < 2^38: (en-1)*83492791 < 2^38 -> en-1 <= 3292
        s_fold = (fold_ok_host && mx <= 3293) ? 1 : 0;
    }
    __syncthreads();

    // block -> (point group, level group); warp -> one level, lane -> point
    const int pg = blockIdx.x >> 2;
    const int lg = blockIdx.x & 3;
    const int l  = lg * 4 + wid;           // warp-uniform
    int n = pg * 32 + lane;
    const bool valid = (n < N);
    if (n >= N) n = N - 1;                 // stay in-bounds, no early exit

    const float px = xyz[3 * n + 0];
    const float py = xyz[3 * n + 1];
    const float pz = xyz[3 * n + 2];
    // t -= start_frame/(total_frame-1); bounds[0][3]=start_frame/total_frame,
    // en[0][3]=total_frame -> shift = b0w*nt/(nt-1). (= 0 here.)
    const float nt = (float)s_en[3];
    const float pw = tt[n] - __fdiv_rn(s_b0[3] * nt, nt - 1.0f);

    // warp-uniform level constants
    const float es0 = s_es[4*l+0], es1 = s_es[4*l+1];
    const float es2 = s_es[4*l+2], es3 = s_es[4*l+3];
    const int   en0 = s_en[4*l+0], en1 = s_en[4*l+1];
    const int   en2 = s_en[4*l+2], en3 = s_en[4*l+3];
    const bool  ish  = (s_hash[l] != 0);
    const bool  fold = (s_fold != 0);

    const float fx = __fdiv_rn(px - s_b0[0], es0);
    const float fy = __fdiv_rn(py - s_b0[1], es1);
    const float fz = __fdiv_rn(pz - s_b0[2], es2);
    const float fw = __fdiv_rn(pw - s_b0[3], es3);

    // low corner: trunc(f) (coords >= 0); high corner: trunc(fp32(f+1.0f))
    // (NOT low+1: the fp32 add may round up across an integer boundary).
    const int bx = (int)fx, by = (int)fy, bz = (int)fz, bw = (int)fw;
    const int hxc = (int)__fadd_rn(fx, 1.0f);
    const int hyc = (int)__fadd_rn(fy, 1.0f);
    const int hzc = (int)__fadd_rn(fz, 1.0f);
    const int hwc = (int)__fadd_rn(fw, 1.0f);

    const float ox = fx - (float)bx;
    const float oy = fy - (float)by;
    const float oz = fz - (float)bz;
    const float ow = fw - (float)bw;

    int cxs[2], cys[2], czs[2], cws[2];
    cxs[0] = min(max(bx, 0), en0 - 1);  cxs[1] = min(max(hxc, 0), en0 - 1);
    cys[0] = min(max(by, 0), en1 - 1);  cys[1] = min(max(hyc, 0), en1 - 1);
    czs[0] = min(max(bz, 0), en2 - 1);  czs[1] = min(max(hzc, 0), en2 - 1);
    cws[0] = min(max(bw, 0), en3 - 1);  cws[1] = min(max(hwc, 0), en3 - 1);

    float wxs[2], wys[2], wzs[2], wws[2];
    wxs[0] = __saturatef(1.0f - ox); wxs[1] = __saturatef(ox);
    wys[0] = __saturatef(1.0f - oy); wys[1] = __saturatef(oy);
    wzs[0] = __saturatef(1.0f - oz); wzs[1] = __saturatef(oz);
    wws[0] = __saturatef(1.0f - ow); wws[1] = __saturatef(ow);

    // 32-bit hash partials: value = coord * prime < 2^38 -> (lo32, hi<64).
    // x contributes only lo (coord < 2^12, prime = 1).
    const unsigned ly[2] = { (unsigned)cys[0] * 19349663u,
                             (unsigned)cys[1] * 19349663u };
    const unsigned hy[2] = { __umulhi((unsigned)cys[0], 19349663u),
                             __umulhi((unsigned)cys[1], 19349663u) };
    const unsigned lz0 = (unsigned)czs[0] * 83492791u;
    const unsigned lz1 = (unsigned)czs[1] * 83492791u;
    const unsigned hz0 = __umulhi((unsigned)czs[0], 83492791u);
    const unsigned hz1 = __umulhi((unsigned)czs[1], 83492791u);
    const unsigned lw0 = (unsigned)cws[0] * 73856093u;
    const unsigned lw1 = (unsigned)cws[1] * 73856093u;
    const unsigned hw0 = __umulhi((unsigned)cws[0], 73856093u);
    const unsigned hw1 = __umulhi((unsigned)cws[1], 73856093u);
    unsigned lzw[4], hzw[4];
    lzw[0] = lz0 ^ lw0;  hzw[0] = hz0 ^ hw0;
    lzw[1] = lz0 ^ lw1;  hzw[1] = hz0 ^ hw1;
    lzw[2] = lz1 ^ lw0;  hzw[2] = hz1 ^ hw0;
    lzw[3] = lz1 ^ lw1;  hzw[3] = hz1 ^ hw1;

    // factored direct partials (direct levels: prod <= T, fits u32)
    const unsigned e23 = (unsigned)en2 * (unsigned)en3;
    unsigned dzw[4];
    dzw[0] = (unsigned)czs[0] * (unsigned)en3 + (unsigned)cws[0];
    dzw[1] = (unsigned)czs[0] * (unsigned)en3 + (unsigned)cws[1];
    dzw[2] = (unsigned)czs[1] * (unsigned)en3 + (unsigned)cws[0];
    dzw[3] = (unsigned)czs[1] * (unsigned)en3 + (unsigned)cws[1];

    const float2* tab = data + (size_t)Tsz * (unsigned)l;

    float acc0 = 0.0f, acc1 = 0.0f;

    // R13 corner order: i = b*8 + j; x-bit = b, y = j>>2, z = (j>>1)&1, w = j&1
    #pragma unroll
    for (int b = 0; b < 2; b++) {
        const unsigned xlo = (unsigned)cxs[b];
        const unsigned dxp = (unsigned)cxs[b] * (unsigned)en1;

        float2 vals[8];
        #pragma unroll
        for (int j = 0; j < 8; j++) {
            const int yb = (j >> 2) & 1;
            const int zw = j & 3;
            unsigned idx;
            if (ish) {                      // warp-uniform branch
                const unsigned lo = xlo ^ ly[yb] ^ lzw[zw];
                const unsigned hi = hy[yb] ^ hzw[zw];
                if (fold) {
                    // a = h >> 19 (funnel), b = h & (2^19-1); exact congruence
                    const unsigned a  = __funnelshift_r(lo, hi, 19);
                    const unsigned bb = lo & 0x7FFFFu;
                    unsigned v = bb + deltaT - delta * a;  // = b + delta*(T-a)
                    unsigned q = __umulhi(v, m32);         // m32 = floor(2^32/T)
                    unsigned r = v - q * Tsz;              // r in [0, 2T)
                    if (r >= Tsz) r -= Tsz;
                    idx = r;
                } else {                    // exact u64 Barrett fallback
                    unsigned long long h = ((unsigned long long)hi << 32) | lo;
                    unsigned long long q = __umul64hi(h, magic);
                    unsigned long long r = h - q * (unsigned long long)Tsz;
                    if (r >= (unsigned long long)Tsz) r -= (unsigned long long)Tsz;
                    if (r >= (unsigned long long)Tsz) r -= (unsigned long long)Tsz;
                    idx = (unsigned)r;
                }
            } else {                        // direct levels: prod <= T
                unsigned d = (dxp + (unsigned)cys[yb]) * e23;
                idx = d + dzw[zw];
            }
            vals[j] = __ldcg(&tab[idx]);    // L2-only: don't thrash L1
        }
        const float wx = wxs[b];
        #pragma unroll
        for (int j = 0; j < 8; j++) {
            const float w = wx * wys[(j >> 2) & 1]
                          * wzs[(j >> 1) & 1] * wws[j & 1];
            acc0 += w * vals[j].x;
            acc1 += w * vals[j].y;
        }
    }

    // stage result; remap to fully-coalesced, sector-dense stores
    s_out[wid][lane] = make_float2(acc0, acc1);
    __syncthreads();

    const int qp = tid >> 2;                // point within group (0..31)
    const int rp = tid & 3;                 // level within block (0..3)
    const int nq = pg * 32 + qp;
    if (nq < N && valid) {
        out[(size_t)nq * 16 + lg * 4 + rp] = s_out[rp][qp];
    }
}

extern "C" void kernel_launch(void* const* d_in, const int* in_sizes, int n_in,
                              void* d_out, int out_size) {
    const float*  xyz    = (const float*)d_in[0];
    const float*  tt     = (const float*)d_in[1];
    const float2* data   = (const float2*)d_in[2];
    const float*  bounds = (const float*)d_in[3];
    // d_in[4] (offsets) is the fixed 16x4 binary corner table -> hard-coded
    const float*  es     = (const float*)d_in[5];
    const int*    en     = (const int*)d_in[6];
    // d_in[7..9]: start_hash / start_frame / total_frame -> derived on device

    const int N = in_sizes[0] / 3;                        // xyz is [N,3]
    const int LF = out_size / N;                          // = L*f = 32
    const unsigned Tsz = (unsigned)(in_sizes[2] / LF);    // data is [L,T,f]
    const unsigned long long magic = 0xFFFFFFFFFFFFFFFFull / (unsigned long long)Tsz;

    // folded-mod constants: valid when 2^19 <= T < 2^19 + 2048
    const int fold_ok = (Tsz >= (1u << 19)) && (Tsz - (1u << 19) < 2048u);
    const unsigned delta  = fold_ok ? (Tsz - (1u << 19)) : 0u;
    const unsigned deltaT = delta * Tsz;
    const unsigned m32    = (unsigned)(0x100000000ull / (unsigned long long)Tsz);

    const int pgroups = (N + 31) / 32;
    const int blocks = pgroups * 4;        // 4 level-groups of 4 levels each
    mh4d_kernel<<<blocks, 128>>>(xyz, tt, data, bounds, es, en,
                                 (float2*)d_out, N, Tsz, magic,
                                 fold_ok, m32, delta, deltaT);
}